// round 3
// baseline (speedup 1.0000x reference)
#include <cuda_runtime.h>
#include <math.h>

#define NL 4
#define BB 64
#define HH 1024
#define SS 256
#define GHH 512
#define H3 (3*HH)
#define KC 32
#define NB 148      // persistent grid: <= SM count so all blocks are co-resident
#define NT 256      // threads per block

// ---------------- device scratch (allocation-free: __device__ globals) ----------------
static __device__ float g_h [NL*BB*HH];    // post-attn hidden state per layer
static __device__ float g_hg[NL*BB*HH];    // GRU cell output (pre-attn)
static __device__ float g_sh[NL*BB*HH];    // sorted GRU output
static __device__ float g_gi[NL*BB*H3];    // inp @ W_ih^T + b_ih
static __device__ float g_gh[NL*BB*H3];    // h   @ W_hh^T + b_hh
static __device__ float g_a1[NL*BB*2*HH];  // se @ w0^T    (flat [b][t*H+o])
static __device__ float g_a2[NL*BB*2*HH];  // w1 out       (flat [b][g*512+o])
static __device__ float g_a3[NL*BB*2*HH];  // relu(w2 out) (flat [b][g*512+o])
static __device__ unsigned g_arrive;
static __device__ unsigned g_gen;

// ---------------- software grid barrier (all NB blocks resident) ----------------------
// __threadfence() is gpu-scope -> emits CCTL.IVALL (L1D flush) on sm_103a, giving both
// release (before arrive) and acquire (after wait) visibility for scratch tensors.
__device__ __forceinline__ void grid_sync()
{
  __syncthreads();
  if (threadIdx.x == 0) {
    unsigned gen = *(volatile unsigned*)&g_gen;   // read BEFORE arriving
    __threadfence();                              // release (+ L1D flush)
    unsigned a = atomicAdd(&g_arrive, 1u);
    if (a == gridDim.x - 1) {
      g_arrive = 0;
      __threadfence();
      *(volatile unsigned*)&g_gen = gen + 1u;     // release the others
    } else {
      while (*(volatile unsigned*)&g_gen == gen) { __nanosleep(32); }
    }
    __threadfence();                              // acquire (+ L1D flush)
  }
  __syncthreads();
}

// ---------------- 64 x TN fp32 GEMM tile: C = A(64,K) @ W(TN,K)^T ----------------------
// 256 threads: tx = tid&15 (col group), ty = tid>>4 (row group). Thread owns 4 x (TN/16).
// GATHER folds the SortAttn shuffle into the A-load: src = (h%4)*512 + g*128 + h/4.
template<int TN, bool GATHER>
__device__ __forceinline__ void gemm_tile(
    const float* __restrict__ A, long lda,
    const float* __restrict__ W, long ldw,
    int K, int g,
    float (&acc)[4][TN/16],
    float (*As)[KC+4], float (*Ws)[KC+4])
{
  const int tid = threadIdx.x;
  const int tx = tid & 15, ty = tid >> 4;
  constexpr int CPT = TN / 16;
#pragma unroll
  for (int i = 0; i < 4; i++)
#pragma unroll
    for (int j = 0; j < CPT; j++) acc[i][j] = 0.f;

  for (int k0 = 0; k0 < K; k0 += KC) {
    __syncthreads();
    if (!GATHER) {
#pragma unroll
      for (int p = 0; p < 2; p++) {
        int i = tid + p*NT;               // 0..511
        int m = i >> 3, c = (i & 7) << 2;
        float4 v = *reinterpret_cast<const float4*>(A + (long)m*lda + k0 + c);
        *reinterpret_cast<float4*>(&As[m][c]) = v;
      }
    } else {
#pragma unroll
      for (int p = 0; p < 8; p++) {
        int i = tid + p*NT;               // 0..2047
        int m = i >> 5, kc = i & 31;
        int h = k0 + kc;
        int src = ((h & 3) << 9) + (g << 7) + (h >> 2);
        As[m][kc] = A[(long)m*lda + src];
      }
    }
#pragma unroll
    for (int p = 0; p < (TN*8)/NT; p++) { // TN=64 -> 2 iters, TN=32 -> 1 iter
      int i = tid + p*NT;
      int n = i >> 3, c = (i & 7) << 2;
      float4 v = *reinterpret_cast<const float4*>(W + (long)n*ldw + k0 + c);
      *reinterpret_cast<float4*>(&Ws[n][c]) = v;
    }
    __syncthreads();
#pragma unroll
    for (int c4 = 0; c4 < KC; c4 += 4) {
      float4 a[4];
#pragma unroll
      for (int i = 0; i < 4; i++)
        a[i] = *reinterpret_cast<const float4*>(&As[ty*4 + i][c4]);
#pragma unroll
      for (int j = 0; j < CPT; j++) {
        float4 w = *reinterpret_cast<const float4*>(&Ws[tx*CPT + j][c4]);
#pragma unroll
        for (int i = 0; i < 4; i++) {
          acc[i][j] = fmaf(a[i].x, w.x, acc[i][j]);
          acc[i][j] = fmaf(a[i].y, w.y, acc[i][j]);
          acc[i][j] = fmaf(a[i].z, w.z, acc[i][j]);
          acc[i][j] = fmaf(a[i].w, w.w, acc[i][j]);
        }
      }
    }
  }
}

// ---------------- init: broadcast hidden0 (L,1,H) -> (L,B,H), reset barrier ------------
__global__ void k_init(const float* __restrict__ h0)
{
  int idx = blockIdx.x*256 + threadIdx.x;
  if (idx == 0) { g_arrive = 0u; g_gen = 0u; }
  int l = idx / (BB*HH);
  int j = idx & (HH-1);
  g_h[idx] = h0[l*HH + j];
}

// ---------------- persistent main kernel: whole sequence, 6 grid-syncs per step --------
__global__ void __launch_bounds__(NT, 1) k_main(
    const float* __restrict__ x,
    const float* __restrict__ Wih, const float* __restrict__ Whh,
    const float* __restrict__ bih, const float* __restrict__ bhh,
    const float* __restrict__ aw0, const float* __restrict__ aw1,
    const float* __restrict__ aw2, const float* __restrict__ aw3,
    float* __restrict__ out, int write_ht)
{
  __shared__ float As[64][KC+4];
  __shared__ float Ws[64][KC+4];
  const int tid = threadIdx.x;
  const int tx = tid & 15, ty = tid >> 4;
  float* s = &As[0][0];                   // 1024-float sort buffer (fits in As)

  for (int step = 0; step < SS + NL - 1; step++) {

    // ---- P1: gi = inp @ Wih^T + bih ; gh = h @ Whh^T + bhh  (384 tile jobs) ----
    for (int job = blockIdx.x; job < NL*2*48; job += NB) {
      int l = job / 96, r = job % 96, mat = r / 48, nt = r % 48;
      int t = step - l; if (t < 0 || t >= SS) continue;
      int n0 = nt * 64;
      const float* A; long lda; const float* W; const float* bias; float* C;
      if (mat == 0) {
        if (l == 0) { A = x + (long)t*HH; lda = (long)SS*HH; }
        else        { A = g_h + (long)(l-1)*BB*HH; lda = HH; }
        W = Wih + (long)l*H3*HH + (long)n0*HH;
        bias = bih + l*H3 + n0;
        C = g_gi + (long)l*BB*H3;
      } else {
        A = g_h + (long)l*BB*HH; lda = HH;
        W = Whh + (long)l*H3*HH + (long)n0*HH;
        bias = bhh + l*H3 + n0;
        C = g_gh + (long)l*BB*H3;
      }
      float acc[4][4];
      gemm_tile<64,false>(A, lda, W, HH, HH, 0, acc, As, Ws);
#pragma unroll
      for (int i = 0; i < 4; i++) {
        int m = ty*4 + i;
#pragma unroll
        for (int j = 0; j < 4; j++) {
          int n = tx*4 + j;
          C[(long)m*H3 + n0 + n] = acc[i][j] + bias[n];
        }
      }
    }
    grid_sync();

    // ---- P2: GRU gate nonlinearity + bitonic sort of each hidden row (256 jobs) ----
    for (int job = blockIdx.x; job < NL*BB; job += NB) {
      int l = job >> 6, b = job & 63;
      int t = step - l; if (t < 0 || t >= SS) continue;
      long gb = (long)(l*BB + b)*H3;
      long hb = (long)(l*BB + b)*HH;
      __syncthreads();                    // protect s reuse across jobs
      for (int j = tid; j < HH; j += NT) {
        float ir = g_gi[gb + j], iz = g_gi[gb + HH + j], in = g_gi[gb + 2*HH + j];
        float hr = g_gh[gb + j], hz = g_gh[gb + HH + j], hn = g_gh[gb + 2*HH + j];
        float rr = 1.f/(1.f + expf(-(ir + hr)));
        float zz = 1.f/(1.f + expf(-(iz + hz)));
        float nn = tanhf(in + rr*hn);
        float hv = (1.f - zz)*nn + zz*g_h[hb + j];
        g_hg[hb + j] = hv;
        s[j] = hv;
      }
      __syncthreads();
      for (int size = 2; size <= HH; size <<= 1) {
        for (int stride = size >> 1; stride > 0; stride >>= 1) {
          for (int p = tid; p < HH/2; p += NT) {
            int pos = 2*p - (p & (stride - 1));
            float a = s[pos], c = s[pos + stride];
            bool desc = (pos & size) != 0;
            if ((a > c) != desc) { s[pos] = c; s[pos + stride] = a; }
          }
          __syncthreads();
        }
      }
      for (int j = tid; j < HH; j += NT) g_sh[hb + j] = s[j];
      __syncthreads();
    }
    grid_sync();

    // ---- P3: a1 = se @ w0^T  (se row0 = hg, row1 = sorted)  (128 jobs) ----
    for (int job = blockIdx.x; job < NL*2*16; job += NB) {
      int l = job / 32, r = job % 32, y = r / 16, nt = r % 16;
      int t = step - l; if (t < 0 || t >= SS) continue;
      int n0 = nt * 64;
      const float* A = (y ? g_sh : g_hg) + (long)l*BB*HH;
      const float* W = aw0 + (long)l*HH*HH + (long)n0*HH;
      float* C = g_a1 + (long)l*BB*2*HH;
      float acc[4][4];
      gemm_tile<64,false>(A, HH, W, HH, HH, 0, acc, As, Ws);
#pragma unroll
      for (int i = 0; i < 4; i++) {
        int m = ty*4 + i;
#pragma unroll
        for (int j = 0; j < 4; j++)
          C[(long)m*2*HH + y*HH + n0 + tx*4 + j] = acc[i][j];
      }
    }
    grid_sync();

    // ---- P4: w1 GEMM with folded shuffle gather  (128 jobs) ----
    for (int job = blockIdx.x; job < NL*4*8; job += NB) {
      int l = job / 32, r = job % 32, g = r / 8, nt = r % 8;
      int t = step - l; if (t < 0 || t >= SS) continue;
      int n0 = nt * 64;
      const float* A = g_a1 + (long)l*BB*2*HH;
      const float* W = aw1 + (long)l*GHH*GHH + (long)n0*GHH;
      float* C = g_a2 + (long)l*BB*2*HH;
      float acc[4][4];
      gemm_tile<64,true>(A, 2*HH, W, GHH, GHH, g, acc, As, Ws);
#pragma unroll
      for (int i = 0; i < 4; i++) {
        int m = ty*4 + i;
#pragma unroll
        for (int j = 0; j < 4; j++)
          C[(long)m*2*HH + g*GHH + n0 + tx*4 + j] = acc[i][j];
      }
    }
    grid_sync();

    // ---- P5: w2 GEMM with folded shuffle gather + ReLU  (128 jobs) ----
    for (int job = blockIdx.x; job < NL*4*8; job += NB) {
      int l = job / 32, r = job % 32, g = r / 8, nt = r % 8;
      int t = step - l; if (t < 0 || t >= SS) continue;
      int n0 = nt * 64;
      const float* A = g_a2 + (long)l*BB*2*HH;
      const float* W = aw2 + (long)l*GHH*GHH + (long)n0*GHH;
      float* C = g_a3 + (long)l*BB*2*HH;
      float acc[4][4];
      gemm_tile<64,true>(A, 2*HH, W, GHH, GHH, g, acc, As, Ws);
#pragma unroll
      for (int i = 0; i < 4; i++) {
        int m = ty*4 + i;
#pragma unroll
        for (int j = 0; j < 4; j++) {
          float v = acc[i][j];
          C[(long)m*2*HH + g*GHH + n0 + tx*4 + j] = v > 0.f ? v : 0.f;
        }
      }
    }
    grid_sync();

    // ---- P6: w3 GEMM (K=2048, 32-wide N tiles) + fused sigmoid gate epilogue ----
    for (int job = blockIdx.x; job < NL*32; job += NB) {
      int l = job / 32, nt = job % 32;
      int t = step - l; if (t < 0 || t >= SS) continue;
      int n0 = nt * 32;
      const float* A = g_a3 + (long)l*BB*2*HH;
      const float* W = aw3 + (long)l*HH*2*HH + (long)n0*2*HH;
      float acc[4][2];
      gemm_tile<32,false>(A, 2*HH, W, 2*HH, 2*HH, 0, acc, As, Ws);
#pragma unroll
      for (int i = 0; i < 4; i++) {
        int b = ty*4 + i;
#pragma unroll
        for (int j = 0; j < 2; j++) {
          int n = n0 + tx*2 + j;
          long hb = (long)(l*BB + b)*HH + n;
          float res = g_hg[hb] * (1.f/(1.f + expf(-acc[i][j])));
          g_h[hb] = res;
          if (l == NL-1) out[((long)b*SS + t)*HH + n] = res;
          if (write_ht && t == SS-1) out[(long)BB*SS*HH + hb] = res;
        }
      }
    }
    grid_sync();
  }
}

// ---------------- host: 2 graph nodes total ------------------------------------------
extern "C" void kernel_launch(void* const* d_in, const int* in_sizes, int n_in,
                              void* d_out, int out_size)
{
  const float* x   = (const float*)d_in[0];
  const float* h0  = (const float*)d_in[1];
  const float* Wih = (const float*)d_in[2];
  const float* Whh = (const float*)d_in[3];
  const float* bih = (const float*)d_in[4];
  const float* bhh = (const float*)d_in[5];
  const float* aw0 = (const float*)d_in[6];
  const float* aw1 = (const float*)d_in[7];
  const float* aw2 = (const float*)d_in[8];
  const float* aw3 = (const float*)d_in[9];
  float* out = (float*)d_out;

  int write_ht = (out_size >= BB*SS*HH + NL*BB*HH) ? 1 : 0;

  k_init<<<NL*BB*HH/256, 256>>>(h0);
  k_main<<<NB, NT>>>(x, Wih, Whh, bih, bhh, aw0, aw1, aw2, aw3, out, write_ht);
}

// round 4
// speedup vs baseline: 4.3121x; 4.3121x over previous
#include <cuda_runtime.h>
#include <math.h>

#define NL 4
#define BB 64
#define HH 1024
#define SS 256
#define GHH 512
#define H3 (3*HH)
#define KC 64
#define KCP 68
#define NB 148      // persistent grid: one block per SM, all co-resident
#define NT 512      // 16 warps
#define SMEM_BYTES ((64 + 128) * KCP * 4)

// ---------------- device scratch (allocation-free: __device__ globals) ----------------
static __device__ float g_h [NL*BB*HH];    // post-attn hidden state per layer
static __device__ float g_hg[NL*BB*HH];    // GRU cell output (pre-attn)
static __device__ float g_sh[NL*BB*HH];    // sorted GRU output
static __device__ float g_gi[NL*BB*H3];    // inp @ W_ih^T + b_ih
static __device__ float g_gh[NL*BB*H3];    // h   @ W_hh^T + b_hh
static __device__ float g_a1[NL*BB*2*HH];  // se @ w0^T    (flat [b][t*H+o])
static __device__ float g_a2[NL*BB*2*HH];  // w1 out       (flat [b][g*512+o])
static __device__ float g_a3[NL*BB*2*HH];  // relu(w2 out) (flat [b][g*512+o])
static __device__ unsigned g_arrive;
static __device__ unsigned g_gen;

// ---------------- software grid barrier (all NB blocks resident) ----------------------
__device__ __forceinline__ void grid_sync()
{
  __syncthreads();
  if (threadIdx.x == 0) {
    unsigned gen = *(volatile unsigned*)&g_gen;   // read BEFORE arriving
    __threadfence();                              // release (gpu scope -> L1D flush)
    unsigned a = atomicAdd(&g_arrive, 1u);
    if (a == gridDim.x - 1) {
      g_arrive = 0;
      __threadfence();
      *(volatile unsigned*)&g_gen = gen + 1u;
    } else {
      while (*(volatile unsigned*)&g_gen == gen) { __nanosleep(32); }
    }
    __threadfence();                              // acquire
  }
  __syncthreads();
}

// ---------------- tf32 helpers ---------------------------------------------------------
__device__ __forceinline__ unsigned f2tf(float v) {
  unsigned r; asm("cvt.rna.tf32.f32 %0, %1;" : "=r"(r) : "f"(v)); return r;
}

__device__ __forceinline__ void mma8(float* c, unsigned a0, unsigned a1,
                                     unsigned a2, unsigned a3,
                                     unsigned b0, unsigned b1) {
  asm volatile(
    "mma.sync.aligned.m16n8k8.row.col.f32.tf32.tf32.f32 "
    "{%0,%1,%2,%3}, {%4,%5,%6,%7}, {%8,%9}, {%0,%1,%2,%3};"
    : "+f"(c[0]), "+f"(c[1]), "+f"(c[2]), "+f"(c[3])
    : "r"(a0), "r"(a1), "r"(a2), "r"(a3), "r"(b0), "r"(b1));
}

// ---------------- 64 x TN TF32 mma GEMM tile: C = A(64,K) @ W(TN,K)^T ------------------
// 512 threads = 16 warps: wm = wid&3 (16 rows each), wn = wid>>2 (TN/4 cols each).
// Register-staged pipeline: store tile k, issue loads for k+1, compute k.
// GATHER folds the SortAttn shuffle into the A-load: src = (h%4)*512 + g*128 + h/4.
template<int TN, bool GATHER>
__device__ __forceinline__ void gemm_mma(
    const float* __restrict__ A, long lda,
    const float* __restrict__ W, long ldw,
    int K, int g, float (*acc)[4],
    unsigned (*As)[KCP], unsigned (*Ws)[KCP])
{
  constexpr int NFR = TN / 32;            // B frags per warp per k8
  constexpr int NW4 = TN * (KC/4) / NT;   // W float4 loads per thread
  const int tid = threadIdx.x;
  const int lane = tid & 31, qr = lane >> 2, qc = lane & 3;
  const int wid = tid >> 5, wm = wid & 3, wn = wid >> 2;
  const int mrow = wm * 16, nbase = wn * (TN / 4);

#pragma unroll
  for (int j = 0; j < NFR; j++)
#pragma unroll
    for (int i = 0; i < 4; i++) acc[j][i] = 0.f;

  float4 a4[2];
  float  ag[8];
  float4 w4[NW4];

  // prologue: stage tile 0
  if (!GATHER) {
#pragma unroll
    for (int p = 0; p < 2; p++) {
      int i = tid + p*NT; int m = i >> 4; int c = (i & 15) << 2;
      a4[p] = *reinterpret_cast<const float4*>(A + (long)m*lda + c);
    }
  } else {
#pragma unroll
    for (int p = 0; p < 8; p++) {
      int i = tid + p*NT; int m = i >> 6; int h = i & 63;
      int src = ((h & 3) << 9) + (g << 7) + (h >> 2);
      ag[p] = A[(long)m*lda + src];
    }
  }
#pragma unroll
  for (int p = 0; p < NW4; p++) {
    int i = tid + p*NT; int n = i >> 4; int c = (i & 15) << 2;
    w4[p] = *reinterpret_cast<const float4*>(W + (long)n*ldw + c);
  }

  for (int k0 = 0; k0 < K; k0 += KC) {
    __syncthreads();                       // previous tile's compute done
    // store staged tile -> smem (cvt.rna to tf32)
    if (!GATHER) {
#pragma unroll
      for (int p = 0; p < 2; p++) {
        int i = tid + p*NT; int m = i >> 4; int c = (i & 15) << 2;
        uint4 v = make_uint4(f2tf(a4[p].x), f2tf(a4[p].y), f2tf(a4[p].z), f2tf(a4[p].w));
        *reinterpret_cast<uint4*>(&As[m][c]) = v;
      }
    } else {
#pragma unroll
      for (int p = 0; p < 8; p++) {
        int i = tid + p*NT; int m = i >> 6; int kc = i & 63;
        As[m][kc] = f2tf(ag[p]);
      }
    }
#pragma unroll
    for (int p = 0; p < NW4; p++) {
      int i = tid + p*NT; int n = i >> 4; int c = (i & 15) << 2;
      uint4 v = make_uint4(f2tf(w4[p].x), f2tf(w4[p].y), f2tf(w4[p].z), f2tf(w4[p].w));
      *reinterpret_cast<uint4*>(&Ws[n][c]) = v;
    }
    __syncthreads();                       // smem tile visible
    // issue loads for next tile before computing (overlap gmem latency)
    int k1 = k0 + KC;
    if (k1 < K) {
      if (!GATHER) {
#pragma unroll
        for (int p = 0; p < 2; p++) {
          int i = tid + p*NT; int m = i >> 4; int c = (i & 15) << 2;
          a4[p] = *reinterpret_cast<const float4*>(A + (long)m*lda + k1 + c);
        }
      } else {
#pragma unroll
        for (int p = 0; p < 8; p++) {
          int i = tid + p*NT; int m = i >> 6; int h = k1 + (i & 63);
          int src = ((h & 3) << 9) + (g << 7) + (h >> 2);
          ag[p] = A[(long)m*lda + src];
        }
      }
#pragma unroll
      for (int p = 0; p < NW4; p++) {
        int i = tid + p*NT; int n = i >> 4; int c = (i & 15) << 2;
        w4[p] = *reinterpret_cast<const float4*>(W + (long)n*ldw + k1 + c);
      }
    }
    // compute this tile: 8 k8 chunks
#pragma unroll
    for (int kk = 0; kk < KC; kk += 8) {
      unsigned a0 = As[mrow + qr    ][kk + qc];
      unsigned a1 = As[mrow + qr + 8][kk + qc];
      unsigned a2 = As[mrow + qr    ][kk + qc + 4];
      unsigned a3 = As[mrow + qr + 8][kk + qc + 4];
#pragma unroll
      for (int j = 0; j < NFR; j++) {
        unsigned b0 = Ws[nbase + j*8 + qr][kk + qc];
        unsigned b1 = Ws[nbase + j*8 + qr][kk + qc + 4];
        mma8(acc[j], a0, a1, a2, a3, b0, b1);
      }
    }
  }
}

// ---------------- init: broadcast hidden0 (L,1,H) -> (L,B,H), reset barrier ------------
__global__ void k_init(const float* __restrict__ h0)
{
  int idx = blockIdx.x*256 + threadIdx.x;
  if (idx == 0) { g_arrive = 0u; g_gen = 0u; }
  int l = idx / (BB*HH);
  int j = idx & (HH-1);
  g_h[idx] = h0[l*HH + j];
}

// ---------------- persistent main kernel ----------------------------------------------
__global__ void __launch_bounds__(NT, 1) k_main(
    const float* __restrict__ x,
    const float* __restrict__ Wih, const float* __restrict__ Whh,
    const float* __restrict__ bih, const float* __restrict__ bhh,
    const float* __restrict__ aw0, const float* __restrict__ aw1,
    const float* __restrict__ aw2, const float* __restrict__ aw3,
    float* __restrict__ out, int write_ht)
{
  extern __shared__ unsigned dynsmem[];
  unsigned (*As)[KCP] = reinterpret_cast<unsigned(*)[KCP]>(dynsmem);
  unsigned (*Ws)[KCP] = reinterpret_cast<unsigned(*)[KCP]>(dynsmem + 64*KCP);
  float* s = reinterpret_cast<float*>(dynsmem);   // 1024-float sort buffer

  const int tid = threadIdx.x;
  const int lane = tid & 31, qr = lane >> 2, qc = lane & 3;
  const int wid = tid >> 5, wm = wid & 3, wn = wid >> 2;
  const int mrow = wm * 16;

  for (int step = 0; step < SS + NL - 1; step++) {

    // ---- P1: gi = inp @ Wih^T + bih ; gh = h @ Whh^T + bhh  (TN=128, 192 jobs) ----
    for (int job = blockIdx.x; job < NL*2*24; job += NB) {
      int l = job / 48, rr = job % 48, mat = rr / 24, nt = rr % 24;
      int t = step - l; if (t < 0 || t >= SS) continue;
      int n0 = nt * 128;
      const float* A; long lda; const float* W; const float* bias; float* C;
      if (mat == 0) {
        if (l == 0) { A = x + (long)t*HH; lda = (long)SS*HH; }
        else        { A = g_h + (long)(l-1)*BB*HH; lda = HH; }
        W = Wih + (long)l*H3*HH + (long)n0*HH;
        bias = bih + l*H3 + n0;
        C = g_gi + (long)l*BB*H3;
      } else {
        A = g_h + (long)l*BB*HH; lda = HH;
        W = Whh + (long)l*H3*HH + (long)n0*HH;
        bias = bhh + l*H3 + n0;
        C = g_gh + (long)l*BB*H3;
      }
      float acc[4][4];
      gemm_mma<128,false>(A, lda, W, HH, HH, 0, acc, As, Ws);
      int nb = wn * 32;
#pragma unroll
      for (int j = 0; j < 4; j++) {
        int nl = nb + j*8 + 2*qc;
        float2 v0 = make_float2(acc[j][0] + bias[nl], acc[j][1] + bias[nl+1]);
        float2 v1 = make_float2(acc[j][2] + bias[nl], acc[j][3] + bias[nl+1]);
        *reinterpret_cast<float2*>(&C[(long)(mrow+qr  )*H3 + n0 + nl]) = v0;
        *reinterpret_cast<float2*>(&C[(long)(mrow+qr+8)*H3 + n0 + nl]) = v1;
      }
    }
    grid_sync();

    // ---- P2: GRU gate nonlinearity + bitonic sort (256 jobs) ----
    for (int job = blockIdx.x; job < NL*BB; job += NB) {
      int l = job >> 6, b = job & 63;
      int t = step - l; if (t < 0 || t >= SS) continue;
      long gb = (long)(l*BB + b)*H3;
      long hb = (long)(l*BB + b)*HH;
      __syncthreads();
      for (int j = tid; j < HH; j += NT) {
        float ir = g_gi[gb + j], iz = g_gi[gb + HH + j], in = g_gi[gb + 2*HH + j];
        float hr = g_gh[gb + j], hz = g_gh[gb + HH + j], hn = g_gh[gb + 2*HH + j];
        float rr = 1.f/(1.f + expf(-(ir + hr)));
        float zz = 1.f/(1.f + expf(-(iz + hz)));
        float nn = tanhf(in + rr*hn);
        float hv = (1.f - zz)*nn + zz*g_h[hb + j];
        g_hg[hb + j] = hv;
        s[j] = hv;
      }
      __syncthreads();
      for (int size = 2; size <= HH; size <<= 1) {
        for (int stride = size >> 1; stride > 0; stride >>= 1) {
          if (tid < HH/2) {
            int p = tid;
            int pos = 2*p - (p & (stride - 1));
            float a = s[pos], c = s[pos + stride];
            bool desc = (pos & size) != 0;
            if ((a > c) != desc) { s[pos] = c; s[pos + stride] = a; }
          }
          __syncthreads();
        }
      }
      for (int j = tid; j < HH; j += NT) g_sh[hb + j] = s[j];
      __syncthreads();
    }
    grid_sync();

    // ---- P3: a1 = se @ w0^T  (TN=64, 128 jobs) ----
    for (int job = blockIdx.x; job < NL*2*16; job += NB) {
      int l = job / 32, rr = job % 32, y = rr / 16, nt = rr % 16;
      int t = step - l; if (t < 0 || t >= SS) continue;
      int n0 = nt * 64;
      const float* A = (y ? g_sh : g_hg) + (long)l*BB*HH;
      const float* W = aw0 + (long)l*HH*HH + (long)n0*HH;
      float* C = g_a1 + (long)l*BB*2*HH;
      float acc[2][4];
      gemm_mma<64,false>(A, HH, W, HH, HH, 0, acc, As, Ws);
      int nb = wn * 16;
#pragma unroll
      for (int j = 0; j < 2; j++) {
        int nl = nb + j*8 + 2*qc;
        *reinterpret_cast<float2*>(&C[(long)(mrow+qr  )*2*HH + y*HH + n0 + nl]) =
            make_float2(acc[j][0], acc[j][1]);
        *reinterpret_cast<float2*>(&C[(long)(mrow+qr+8)*2*HH + y*HH + n0 + nl]) =
            make_float2(acc[j][2], acc[j][3]);
      }
    }
    grid_sync();

    // ---- P4: w1 GEMM with folded shuffle gather (TN=64, 128 jobs) ----
    for (int job = blockIdx.x; job < NL*4*8; job += NB) {
      int l = job / 32, rr = job % 32, g4 = rr / 8, nt = rr % 8;
      int t = step - l; if (t < 0 || t >= SS) continue;
      int n0 = nt * 64;
      const float* A = g_a1 + (long)l*BB*2*HH;
      const float* W = aw1 + (long)l*GHH*GHH + (long)n0*GHH;
      float* C = g_a2 + (long)l*BB*2*HH;
      float acc[2][4];
      gemm_mma<64,true>(A, 2*HH, W, GHH, GHH, g4, acc, As, Ws);
      int nb = wn * 16;
#pragma unroll
      for (int j = 0; j < 2; j++) {
        int nl = nb + j*8 + 2*qc;
        *reinterpret_cast<float2*>(&C[(long)(mrow+qr  )*2*HH + g4*GHH + n0 + nl]) =
            make_float2(acc[j][0], acc[j][1]);
        *reinterpret_cast<float2*>(&C[(long)(mrow+qr+8)*2*HH + g4*GHH + n0 + nl]) =
            make_float2(acc[j][2], acc[j][3]);
      }
    }
    grid_sync();

    // ---- P5: w2 GEMM with folded shuffle gather + ReLU (TN=64, 128 jobs) ----
    for (int job = blockIdx.x; job < NL*4*8; job += NB) {
      int l = job / 32, rr = job % 32, g4 = rr / 8, nt = rr % 8;
      int t = step - l; if (t < 0 || t >= SS) continue;
      int n0 = nt * 64;
      const float* A = g_a2 + (long)l*BB*2*HH;
      const float* W = aw2 + (long)l*GHH*GHH + (long)n0*GHH;
      float* C = g_a3 + (long)l*BB*2*HH;
      float acc[2][4];
      gemm_mma<64,true>(A, 2*HH, W, GHH, GHH, g4, acc, As, Ws);
      int nb = wn * 16;
#pragma unroll
      for (int j = 0; j < 2; j++) {
        int nl = nb + j*8 + 2*qc;
        float2 v0 = make_float2(fmaxf(acc[j][0],0.f), fmaxf(acc[j][1],0.f));
        float2 v1 = make_float2(fmaxf(acc[j][2],0.f), fmaxf(acc[j][3],0.f));
        *reinterpret_cast<float2*>(&C[(long)(mrow+qr  )*2*HH + g4*GHH + n0 + nl]) = v0;
        *reinterpret_cast<float2*>(&C[(long)(mrow+qr+8)*2*HH + g4*GHH + n0 + nl]) = v1;
      }
    }
    grid_sync();

    // ---- P6: w3 GEMM (K=2048, TN=32, 128 jobs) + fused sigmoid gate ----
    for (int job = blockIdx.x; job < NL*32; job += NB) {
      int l = job / 32, nt = job % 32;
      int t = step - l; if (t < 0 || t >= SS) continue;
      int n0 = nt * 32;
      const float* A = g_a3 + (long)l*BB*2*HH;
      const float* W = aw3 + (long)l*HH*2*HH + (long)n0*2*HH;
      float acc[1][4];
      gemm_mma<32,false>(A, 2*HH, W, 2*HH, 2*HH, 0, acc, As, Ws);
      int nl = wn*8 + 2*qc;
      int n = n0 + nl;
#pragma unroll
      for (int half = 0; half < 2; half++) {
        int b = mrow + qr + half*8;
        long hb = (long)(l*BB + b)*HH + n;
#pragma unroll
        for (int jj = 0; jj < 2; jj++) {
          float a = acc[0][half*2 + jj];
          float res = g_hg[hb + jj] * (1.f/(1.f + expf(-a)));
          g_h[hb + jj] = res;
          if (l == NL-1) out[((long)b*SS + t)*HH + n + jj] = res;
          if (write_ht && t == SS-1) out[(long)BB*SS*HH + hb + jj] = res;
        }
      }
    }
    grid_sync();
  }
}

// ---------------- host: 2 graph nodes total -------------------------------------------
extern "C" void kernel_launch(void* const* d_in, const int* in_sizes, int n_in,
                              void* d_out, int out_size)
{
  const float* x   = (const float*)d_in[0];
  const float* h0  = (const float*)d_in[1];
  const float* Wih = (const float*)d_in[2];
  const float* Whh = (const float*)d_in[3];
  const float* bih = (const float*)d_in[4];
  const float* bhh = (const float*)d_in[5];
  const float* aw0 = (const float*)d_in[6];
  const float* aw1 = (const float*)d_in[7];
  const float* aw2 = (const float*)d_in[8];
  const float* aw3 = (const float*)d_in[9];
  float* out = (float*)d_out;

  int write_ht = (out_size >= BB*SS*HH + NL*BB*HH) ? 1 : 0;

  cudaFuncSetAttribute(k_main, cudaFuncAttributeMaxDynamicSharedMemorySize, SMEM_BYTES);

  k_init<<<NL*BB*HH/256, 256>>>(h0);
  k_main<<<NB, NT, SMEM_BYTES>>>(x, Wih, Whh, bih, bhh, aw0, aw1, aw2, aw3, out, write_ht);
}